// round 15
// baseline (speedup 1.0000x reference)
#include <cuda_runtime.h>
#include <cuda_bf16.h>
#include <cstdint>

#define HID   64
#define NFLD  2
#define NHH   32
#define NMF   8
#define NTS   4
#define NLAY  9
#define MAXN  10016

// ---------------- scratch (device globals; no allocation allowed) -----------
__device__ float g_Ptop[MAXN * HID];
__device__ float g_Pbot[MAXN * HID];
__device__ float g_acc [MAXN * HID];
__device__ float g_meshh[MAXN * NHH];
__device__ float g_Fprev[MAXN * NFLD];
// pre-converted edge weights: [set][layer][n][k] bf16 hi/lo, chunk-swizzled
__device__ __align__(16) __nv_bfloat16 g_WBhi[2][NLAY * HID * HID];
__device__ __align__(16) __nv_bfloat16 g_WBlo[2][NLAY * HID * HID];

// ---------------- helpers -----------------------------------------------------
__device__ __forceinline__ uint32_t s2u(const void* p) {
    uint32_t a;
    asm("{ .reg .u64 t; cvta.to.shared.u64 t, %1; cvt.u32.u64 %0, t; }"
        : "=r"(a) : "l"(p));
    return a;
}
__device__ __forceinline__ void ldsm4(uint32_t* r, uint32_t addr) {
    asm volatile("ldmatrix.sync.aligned.m8n8.x4.shared.b16 {%0,%1,%2,%3}, [%4];"
                 : "=r"(r[0]), "=r"(r[1]), "=r"(r[2]), "=r"(r[3]) : "r"(addr));
}
__device__ __forceinline__ void stsm4(uint32_t addr, uint32_t r0, uint32_t r1,
                                      uint32_t r2, uint32_t r3) {
    asm volatile("stmatrix.sync.aligned.m8n8.x4.shared.b16 [%0], {%1,%2,%3,%4};"
                 :: "r"(addr), "r"(r0), "r"(r1), "r"(r2), "r"(r3) : "memory");
}
__device__ __forceinline__ void mma16816(float* c, const uint32_t* a, const uint32_t* b) {
    asm volatile("mma.sync.aligned.m16n8k16.row.col.f32.bf16.bf16.f32 "
                 "{%0,%1,%2,%3}, {%4,%5,%6,%7}, {%8,%9}, {%0,%1,%2,%3};"
                 : "+f"(c[0]), "+f"(c[1]), "+f"(c[2]), "+f"(c[3])
                 : "r"(a[0]), "r"(a[1]), "r"(a[2]), "r"(a[3]), "r"(b[0]), "r"(b[1]));
}
__device__ __forceinline__ uint32_t cvt2bf(float lo, float hi_) {
    uint32_t r;
    asm("cvt.rn.bf16x2.f32 %0, %1, %2;" : "=r"(r) : "f"(hi_), "f"(lo));
    return r;
}
#define CP_ASYNC16(dst, src) \
    asm volatile("cp.async.ca.shared.global [%0], [%1], 16;" :: "r"(dst), "l"(src) : "memory")
#define CP_COMMIT() asm volatile("cp.async.commit_group;" ::: "memory")
#define CP_WAIT0()  asm volatile("cp.async.wait_group 0;" ::: "memory")

// ---------------- weight pre-conversion (both sets, one launch) --------------
__global__ void prep_wb_kernel(const float* __restrict__ W_md,
                               const float* __restrict__ W_ds,
                               __nv_bfloat16* __restrict__ hi,
                               __nv_bfloat16* __restrict__ lo)
{
    int idx = blockIdx.x * 256 + threadIdx.x;
    if (idx >= 2 * NLAY * HID * HID) return;
    int set = idx >= NLAY * HID * HID;
    int r0  = idx - set * NLAY * HID * HID;
    const float* Wh = set ? W_ds : W_md;
    int l = r0 >> 12, r = r0 & 4095;
    int j = r >> 6, k = r & 63;
    float w = Wh[l * 4096 + k * 64 + j];
    __nv_bfloat16 h = __float2bfloat16(w);
    __nv_bfloat16 lo_ = __float2bfloat16(w - __bfloat162float(h));
    int off = j * 128 + k * 2;
    int sw  = off ^ ((off >> 3) & 0x70);
    hi[set * NLAY * HID * HID + l * 4096 + (sw >> 1)] = h;
    lo[set * NLAY * HID * HID + l * 4096 + (sw >> 1)] = lo_;
}

// ---------------- per-node projection (mesh descriptor) ----------------------
__global__ void proj_md_kernel(const float* __restrict__ X,
                               const float* __restrict__ W0,
                               float* __restrict__ Ptop, float* __restrict__ Pbot,
                               float* __restrict__ acc, int Nn)
{
    int idx = blockIdx.x * blockDim.x + threadIdx.x;
    if (idx >= Nn * HID) return;
    int n = idx >> 6, j = idx & 63;
    float st0 = 0.f, st1 = 0.f, sb0 = 0.f, sb1 = 0.f;
#pragma unroll
    for (int k = 0; k < NMF; k += 2) {
        float x0 = X[n * NMF + k], x1 = X[n * NMF + k + 1];
        st0 = fmaf(x0, W0[k * HID + j], st0);
        st1 = fmaf(x1, W0[(k + 1) * HID + j], st1);
        sb0 = fmaf(x0, W0[(NMF + k) * HID + j], sb0);
        sb1 = fmaf(x1, W0[(NMF + k + 1) * HID + j], sb1);
    }
    Ptop[idx] = st0 + st1;
    Pbot[idx] = sb0 + sb1;
    acc[idx]  = 0.f;
}

// ---------------- fused node kernel: mesh decoder + encoder(t=1) + proj ------
// 16 nodes per block (256 threads), decoder weights amortized 4x.
__global__ void fused_md_kernel(const float* __restrict__ acc_in,
                                const float* __restrict__ dw1, const float* __restrict__ db1,
                                const float* __restrict__ dw2, const float* __restrict__ db2,
                                float* __restrict__ meshh,
                                const float* __restrict__ Fprev,      // F_initial
                                const float* __restrict__ Fb, int t,
                                const float* __restrict__ encW,
                                const float* __restrict__ encb,
                                const float* __restrict__ W0,
                                float* __restrict__ Ptop, float* __restrict__ Pbot,
                                float* __restrict__ acc_z, int Nn)
{
    __shared__ float t1[16][64];
    __shared__ float mh[16][32];
    __shared__ float he[16][64];
    int tid = threadIdx.x;
    int j = tid & 63, q = tid >> 6;
    int nb = blockIdx.x * 16;

    // stage 1: t1 = relu(acc@dw1+db1) for 16 nodes
#pragma unroll
    for (int it = 0; it < 4; it++) {
        int ln = it * 4 + q, n = nb + ln;
        float s0 = db1[j], s1 = 0.f;
        if (n < Nn) {
#pragma unroll 8
            for (int k = 0; k < HID; k += 2) {
                s0 = fmaf(acc_in[n * HID + k],     dw1[k * HID + j],       s0);
                s1 = fmaf(acc_in[n * HID + k + 1], dw1[(k + 1) * HID + j], s1);
            }
        }
        t1[ln][j] = fmaxf(s0 + s1, 0.f);
    }
    __syncthreads();

    // stage 2: meshh = t1@dw2+db2 (16 nodes x 32 cols = 512 slots)
#pragma unroll
    for (int lp = 0; lp < 2; lp++) {
        int idx = lp * 256 + tid;
        int ln = idx >> 5, j2 = idx & 31;
        int n = nb + ln;
        if (n < Nn) {
            float o0 = db2[j2], o1 = 0.f;
#pragma unroll 8
            for (int k = 0; k < HID; k += 2) {
                o0 = fmaf(t1[ln][k],     dw2[k * NHH + j2],       o0);
                o1 = fmaf(t1[ln][k + 1], dw2[(k + 1) * NHH + j2], o1);
            }
            float o = o0 + o1;
            mh[ln][j2] = o;
            meshh[n * NHH + j2] = o;
        }
    }
    __syncthreads();

    // stage 3: encoder henc = relu([mh, Fprev, Fb]@encW+encb)
#pragma unroll
    for (int it = 0; it < 4; it++) {
        int ln = it * 4 + q, n = nb + ln;
        float s0 = encb[j], s1 = 0.f;
        if (n < Nn) {
#pragma unroll
            for (int k = 0; k < NHH; k += 2) {
                s0 = fmaf(mh[ln][k],     encW[k * HID + j],       s0);
                s1 = fmaf(mh[ln][k + 1], encW[(k + 1) * HID + j], s1);
            }
            s0 = fmaf(Fprev[n * NFLD + 0], encW[(NHH + 0) * HID + j], s0);
            s1 = fmaf(Fprev[n * NFLD + 1], encW[(NHH + 1) * HID + j], s1);
            s0 = fmaf(Fb[n * NTS + t],     encW[(NHH + 2) * HID + j], s0);
        }
        he[ln][j] = fmaxf(s0 + s1, 0.f);
    }
    __syncthreads();

    // stage 4: proj Ptop/Pbot + zero acc
#pragma unroll
    for (int it = 0; it < 4; it++) {
        int ln = it * 4 + q, n = nb + ln;
        if (n < Nn) {
            float st0 = 0.f, st1 = 0.f, sb0 = 0.f, sb1 = 0.f;
#pragma unroll 8
            for (int k = 0; k < HID; k += 2) {
                float x0 = he[ln][k], x1 = he[ln][k + 1];
                st0 = fmaf(x0, W0[k * HID + j], st0);
                st1 = fmaf(x1, W0[(k + 1) * HID + j], st1);
                sb0 = fmaf(x0, W0[(HID + k) * HID + j], sb0);
                sb1 = fmaf(x1, W0[(HID + k + 1) * HID + j], sb1);
            }
            int idx = n * HID + j;
            Ptop[idx] = st0 + st1;
            Pbot[idx] = sb0 + sb1;
            acc_z[idx] = 0.f;
        }
    }
}

// ---------------- fused node kernel: ds decoder + Euler + encoder(t) + proj --
// has_enc = 0 for the final timestep (no next edge pass).
__global__ void fused_ds_kernel(const float* __restrict__ acc_in,
                                const float* __restrict__ dw1, const float* __restrict__ db1,
                                const float* __restrict__ dw2, const float* __restrict__ db2,
                                const float* __restrict__ Fprev_in,
                                const float* __restrict__ dtp,
                                float* __restrict__ Fprev_out,
                                float* __restrict__ outF, float* __restrict__ outFd,
                                int step, int nsteps,
                                int has_enc,
                                const float* __restrict__ meshh,
                                const float* __restrict__ Fb, int t,
                                const float* __restrict__ encW,
                                const float* __restrict__ encb,
                                const float* __restrict__ W0,
                                float* __restrict__ Ptop, float* __restrict__ Pbot,
                                float* __restrict__ acc_z, int Nn)
{
    __shared__ float t1[16][64];
    __shared__ float fc_s[16][2];
    __shared__ float he[16][64];
    int tid = threadIdx.x;
    int j = tid & 63, q = tid >> 6;
    int nb = blockIdx.x * 16;

    // stage 1: t1 = relu(acc@dw1+db1)
#pragma unroll
    for (int it = 0; it < 4; it++) {
        int ln = it * 4 + q, n = nb + ln;
        float s0 = db1[j], s1 = 0.f;
        if (n < Nn) {
#pragma unroll 8
            for (int k = 0; k < HID; k += 2) {
                s0 = fmaf(acc_in[n * HID + k],     dw1[k * HID + j],       s0);
                s1 = fmaf(acc_in[n * HID + k + 1], dw1[(k + 1) * HID + j], s1);
            }
        }
        t1[ln][j] = fmaxf(s0 + s1, 0.f);
    }
    __syncthreads();

    // stage 2: F_dot, Euler step, outputs (16 nodes x 2 fields = 32 slots)
    if (tid < 32) {
        int ln = tid >> 1, f = tid & 1;
        int n = nb + ln;
        if (n < Nn) {
            float o0 = db2[f], o1 = 0.f;
#pragma unroll 8
            for (int k = 0; k < HID; k += 2) {
                o0 = fmaf(t1[ln][k],     dw2[k * NFLD + f],       o0);
                o1 = fmaf(t1[ln][k + 1], dw2[(k + 1) * NFLD + f], o1);
            }
            float o  = o0 + o1;
            float fp = Fprev_in[n * NFLD + f];
            float fcv = fmaf(dtp[0], o, fp);
            outF [(n * nsteps + step) * NFLD + f] = fcv;
            outFd[(n * nsteps + step) * NFLD + f] = o;
            Fprev_out[n * NFLD + f] = fcv;
            fc_s[ln][f] = fcv;
        }
    }
    if (!has_enc) return;
    __syncthreads();

    // stage 3: encoder using just-computed F_cur
#pragma unroll
    for (int it = 0; it < 4; it++) {
        int ln = it * 4 + q, n = nb + ln;
        float s0 = encb[j], s1 = 0.f;
        if (n < Nn) {
#pragma unroll
            for (int k = 0; k < NHH; k += 2) {
                s0 = fmaf(meshh[n * NHH + k],     encW[k * HID + j],       s0);
                s1 = fmaf(meshh[n * NHH + k + 1], encW[(k + 1) * HID + j], s1);
            }
            s0 = fmaf(fc_s[ln][0],  encW[(NHH + 0) * HID + j], s0);
            s1 = fmaf(fc_s[ln][1],  encW[(NHH + 1) * HID + j], s1);
            s0 = fmaf(Fb[n * NTS + t], encW[(NHH + 2) * HID + j], s0);
        }
        he[ln][j] = fmaxf(s0 + s1, 0.f);
    }
    __syncthreads();

    // stage 4: proj Ptop/Pbot + zero acc
#pragma unroll
    for (int it = 0; it < 4; it++) {
        int ln = it * 4 + q, n = nb + ln;
        if (n < Nn) {
            float st0 = 0.f, st1 = 0.f, sb0 = 0.f, sb1 = 0.f;
#pragma unroll 8
            for (int k = 0; k < HID; k += 2) {
                float x0 = he[ln][k], x1 = he[ln][k + 1];
                st0 = fmaf(x0, W0[k * HID + j], st0);
                st1 = fmaf(x1, W0[(k + 1) * HID + j], st1);
                sb0 = fmaf(x0, W0[(HID + k) * HID + j], sb0);
                sb1 = fmaf(x1, W0[(HID + k + 1) * HID + j], sb1);
            }
            int idx = n * HID + j;
            Ptop[idx] = st0 + st1;
            Pbot[idx] = sb0 + sb1;
            acc_z[idx] = 0.f;
        }
    }
}

// ---------------- HMMA edge MLP + scatter (unchanged from R13) ----------------
#define SM_A0HI  0
#define SM_A0LO  16384
#define SM_A1HI  32768
#define SM_A1LO  49152
#define SM_W0HI  65536
#define SM_W0LO  73728
#define SM_W1HI  81920
#define SM_W1LO  90112
#define SM_BIAS  98304
#define SM_TOTAL (98304 + NLAY * HID * 4)   // 100608

__global__ void __launch_bounds__(256, 2)
edge_mlp_tc_kernel(const float* __restrict__ Ptop, const float* __restrict__ Pbot,
                   const float* __restrict__ b0,
                   const __nv_bfloat16* __restrict__ WBhi,
                   const __nv_bfloat16* __restrict__ WBlo,
                   const float* __restrict__ Bh,
                   const int* __restrict__ srcp, const int* __restrict__ dstp,
                   float* __restrict__ acc, int E)
{
    extern __shared__ __align__(1024) char sm[];
    const int tid = threadIdx.x, lane = tid & 31, wid = tid >> 5;
    const int eb = wid & 3, cb = wid >> 2;
    const int e0 = blockIdx.x * 128;

    // ---- gather h0 = relu(Ptop[dst]+Pbot[src]+b0), split -> A0 hi/lo ----
    for (int u = tid; u < 128 * 8; u += 256) {
        int e = u & 127, oct = u >> 7;
        int ge = e0 + e;
        float v[8];
        if (ge < E) {
            int d = dstp[ge], s = srcp[ge];
            float4 t0 = *(const float4*)(Ptop + d * HID + oct * 8);
            float4 t1 = *(const float4*)(Ptop + d * HID + oct * 8 + 4);
            float4 p0 = *(const float4*)(Pbot + s * HID + oct * 8);
            float4 p1 = *(const float4*)(Pbot + s * HID + oct * 8 + 4);
            float4 c0 = *(const float4*)(b0 + oct * 8);
            float4 c1 = *(const float4*)(b0 + oct * 8 + 4);
            v[0] = fmaxf(t0.x + p0.x + c0.x, 0.f);
            v[1] = fmaxf(t0.y + p0.y + c0.y, 0.f);
            v[2] = fmaxf(t0.z + p0.z + c0.z, 0.f);
            v[3] = fmaxf(t0.w + p0.w + c0.w, 0.f);
            v[4] = fmaxf(t1.x + p1.x + c1.x, 0.f);
            v[5] = fmaxf(t1.y + p1.y + c1.y, 0.f);
            v[6] = fmaxf(t1.z + p1.z + c1.z, 0.f);
            v[7] = fmaxf(t1.w + p1.w + c1.w, 0.f);
        } else {
#pragma unroll
            for (int i = 0; i < 8; i++) v[i] = 0.f;
        }
        uint32_t hw[4], lw[4];
#pragma unroll
        for (int i = 0; i < 4; i++) {
            float a = v[2 * i], b = v[2 * i + 1];
            uint32_t h = cvt2bf(a, b);
            float haf = __uint_as_float(h << 16);
            float hbf = __uint_as_float(h & 0xFFFF0000u);
            hw[i] = h;
            lw[i] = cvt2bf(a - haf, b - hbf);
        }
        int sw = (oct ^ (e & 7)) * 16;
        *(uint4*)(sm + SM_A0HI + e * 128 + sw) = make_uint4(hw[0], hw[1], hw[2], hw[3]);
        *(uint4*)(sm + SM_A0LO + e * 128 + sw) = make_uint4(lw[0], lw[1], lw[2], lw[3]);
    }

    // ---- stage layer-0 weights (cp.async) + all biases ----
    {
        uint32_t wh = s2u(sm + SM_W0HI), wl = s2u(sm + SM_W0LO);
        const char* gh = (const char*)WBhi;
        const char* gl = (const char*)WBlo;
        for (int i = tid; i < 512; i += 256) {
            CP_ASYNC16(wh + i * 16, gh + i * 16);
            CP_ASYNC16(wl + i * 16, gl + i * 16);
        }
        CP_COMMIT();
        for (int i = tid; i < NLAY * HID; i += 256)
            ((float*)(sm + SM_BIAS))[i] = Bh[i];
    }
    CP_WAIT0();
    __syncthreads();

    const int rA  = lane & 15, khA = lane >> 4;
    const int nB0 = cb * 32 + (lane & 7) + ((lane >> 4) << 3);
    const int khB = (lane >> 3) & 1;
    const int sli = lane & 7, smm = lane >> 3;
    const uint32_t st_base =
        (uint32_t)((eb * 32 + sli) * 128 + (((cb * 4 + smm) ^ sli) << 4));

    uint32_t ArdHi = s2u(sm + SM_A0HI);
    uint32_t AwrHi = s2u(sm + SM_A1HI);

    for (int l = 0; l < NLAY; l++) {
        const uint32_t WhiB = s2u(sm + ((l & 1) ? SM_W1HI : SM_W0HI));
        const uint32_t WloB = s2u(sm + ((l & 1) ? SM_W1LO : SM_W0LO));

        if (l + 1 < NLAY) {
            uint32_t wh = s2u(sm + ((l & 1) ? SM_W0HI : SM_W1HI));
            uint32_t wl = s2u(sm + ((l & 1) ? SM_W0LO : SM_W1LO));
            const char* gh = (const char*)(WBhi + (l + 1) * 4096);
            const char* gl = (const char*)(WBlo + (l + 1) * 4096);
            for (int i = tid; i < 512; i += 256) {
                CP_ASYNC16(wh + i * 16, gh + i * 16);
                CP_ASYNC16(wl + i * 16, gl + i * 16);
            }
            CP_COMMIT();
        }

        const float* bsl = (const float*)(sm + SM_BIAS) + l * HID;
        float C[2][4][4];
#pragma unroll
        for (int nt = 0; nt < 4; nt++) {
            float2 bb = *(const float2*)(bsl + cb * 32 + nt * 8 + (lane & 3) * 2);
#pragma unroll
            for (int mt = 0; mt < 2; mt++) {
                C[mt][nt][0] = bb.x; C[mt][nt][1] = bb.y;
                C[mt][nt][2] = bb.x; C[mt][nt][3] = bb.y;
            }
        }

#pragma unroll
        for (int kt = 0; kt < 4; kt++) {
            uint32_t ah[2][4], al[2][4], bh[4][2], bl[4][2];
#pragma unroll
            for (int mt = 0; mt < 2; mt++) {
                int e = eb * 32 + rA + mt * 16;
                uint32_t off = (uint32_t)(e * 128 + ((((kt << 1) + khA) ^ (e & 7)) << 4));
                ldsm4(ah[mt], ArdHi + off);
                ldsm4(al[mt], ArdHi + 16384 + off);
            }
#pragma unroll
            for (int np = 0; np < 2; np++) {
                int n = nB0 + np * 16;
                uint32_t off = (uint32_t)(n * 128 + ((((kt << 1) + khB) ^ (n & 7)) << 4));
                uint32_t t4[4];
                ldsm4(t4, WhiB + off);
                bh[np * 2][0] = t4[0]; bh[np * 2][1] = t4[1];
                bh[np * 2 + 1][0] = t4[2]; bh[np * 2 + 1][1] = t4[3];
                ldsm4(t4, WloB + off);
                bl[np * 2][0] = t4[0]; bl[np * 2][1] = t4[1];
                bl[np * 2 + 1][0] = t4[2]; bl[np * 2 + 1][1] = t4[3];
            }
#pragma unroll
            for (int mt = 0; mt < 2; mt++)
#pragma unroll
                for (int nt = 0; nt < 4; nt++) {
                    mma16816(C[mt][nt], ah[mt], bh[nt]);
                    mma16816(C[mt][nt], al[mt], bh[nt]);
                    mma16816(C[mt][nt], ah[mt], bl[nt]);
                }
        }

        if (l + 1 < NLAY) {
#pragma unroll
            for (int mt = 0; mt < 2; mt++) {
#pragma unroll
                for (int half = 0; half < 2; half++) {
                    uint32_t hw[4], lw[4];
#pragma unroll
                    for (int nt = 0; nt < 4; nt++) {
                        float v0 = fmaxf(C[mt][nt][half * 2 + 0], 0.f);
                        float v1 = fmaxf(C[mt][nt][half * 2 + 1], 0.f);
                        uint32_t h = cvt2bf(v0, v1);
                        float h0f = __uint_as_float(h << 16);
                        float h1f = __uint_as_float(h & 0xFFFF0000u);
                        hw[nt] = h;
                        lw[nt] = cvt2bf(v0 - h0f, v1 - h1f);
                    }
                    uint32_t ad = AwrHi + st_base + (uint32_t)(mt * 2048 + half * 1024);
                    stsm4(ad,         hw[0], hw[1], hw[2], hw[3]);
                    stsm4(ad + 16384, lw[0], lw[1], lw[2], lw[3]);
                }
            }
            CP_WAIT0();
            __syncthreads();
            uint32_t t = ArdHi; ArdHi = AwrHi; AwrHi = t;
        } else {
#pragma unroll
            for (int mt = 0; mt < 2; mt++) {
#pragma unroll
                for (int half = 0; half < 2; half++) {
                    int e  = eb * 32 + mt * 16 + (lane >> 2) + half * 8;
                    int ge = e0 + e;
                    if (ge < E) {
                        int node = srcp[ge];
                        float* ap = acc + node * HID;
#pragma unroll
                        for (int nt = 0; nt < 4; nt++) {
                            int n = cb * 32 + nt * 8 + (lane & 3) * 2;
                            atomicAdd(ap + n,     C[mt][nt][half * 2 + 0]);
                            atomicAdd(ap + n + 1, C[mt][nt][half * 2 + 1]);
                        }
                    }
                }
            }
        }
    }
}

// ---------------- launch ------------------------------------------------------
extern "C" void kernel_launch(void* const* d_in, const int* in_sizes, int n_in,
                              void* d_out, int out_size)
{
    const float* F_initial     = (const float*)d_in[0];
    const float* mesh_features = (const float*)d_in[1];
    const int*   edge_index    = (const int*)  d_in[2];
    const float* F_boundary    = (const float*)d_in[3];
    const float* dtp           = (const float*)d_in[4];
    const float* md_w0  = (const float*)d_in[5];
    const float* md_b0  = (const float*)d_in[6];
    const float* md_wh  = (const float*)d_in[7];
    const float* md_bh  = (const float*)d_in[8];
    const float* md_dw1 = (const float*)d_in[9];
    const float* md_db1 = (const float*)d_in[10];
    const float* md_dw2 = (const float*)d_in[11];
    const float* md_db2 = (const float*)d_in[12];
    const float* ds_encw = (const float*)d_in[13];
    const float* ds_encb = (const float*)d_in[14];
    const float* ds_w0  = (const float*)d_in[15];
    const float* ds_b0  = (const float*)d_in[16];
    const float* ds_wh  = (const float*)d_in[17];
    const float* ds_bh  = (const float*)d_in[18];
    const float* ds_dw1 = (const float*)d_in[19];
    const float* ds_db1 = (const float*)d_in[20];
    const float* ds_dw2 = (const float*)d_in[21];
    const float* ds_db2 = (const float*)d_in[22];

    int Nn = in_sizes[0] / NFLD;
    int E  = in_sizes[2] / 2;

    float *Ptop, *Pbot, *acc, *meshh, *Fprev;
    __nv_bfloat16 *wbhi, *wblo;
    cudaGetSymbolAddress((void**)&Ptop,  g_Ptop);
    cudaGetSymbolAddress((void**)&Pbot,  g_Pbot);
    cudaGetSymbolAddress((void**)&acc,   g_acc);
    cudaGetSymbolAddress((void**)&meshh, g_meshh);
    cudaGetSymbolAddress((void**)&Fprev, g_Fprev);
    cudaGetSymbolAddress((void**)&wbhi,  g_WBhi);
    cudaGetSymbolAddress((void**)&wblo,  g_WBlo);

    cudaFuncSetAttribute(edge_mlp_tc_kernel,
                         cudaFuncAttributeMaxDynamicSharedMemorySize, SM_TOTAL);

    const int* srcp = edge_index;
    const int* dstp = edge_index + E;

    int nb_node = (Nn * HID + 255) / 256;
    int nb_fuse = (Nn + 15) / 16;
    int nsteps  = NTS - 1;
    int nb_edge = (E + 127) / 128;
    int nb_prep = (2 * NLAY * HID * HID + 255) / 256;

    float* outF  = (float*)d_out;
    float* outFd = outF + (size_t)out_size / 2;

    __nv_bfloat16* wbhi_md = wbhi;
    __nv_bfloat16* wblo_md = wblo;
    __nv_bfloat16* wbhi_ds = wbhi + NLAY * HID * HID;
    __nv_bfloat16* wblo_ds = wblo + NLAY * HID * HID;

    // ---- weight pre-conversion ----
    prep_wb_kernel<<<nb_prep, 256>>>(md_wh, ds_wh, wbhi, wblo);

    // ---- mesh descriptor pass ----
    proj_md_kernel<<<nb_node, 256>>>(mesh_features, md_w0, Ptop, Pbot, acc, Nn);
    edge_mlp_tc_kernel<<<nb_edge, 256, SM_TOTAL>>>(Ptop, Pbot, md_b0,
                                                   wbhi_md, wblo_md, md_bh,
                                                   srcp, dstp, acc, E);
    // mesh decoder + encoder(t=1) + proj, fused
    fused_md_kernel<<<nb_fuse, 256>>>(acc, md_dw1, md_db1, md_dw2, md_db2, meshh,
                                      F_initial, F_boundary, 1,
                                      ds_encw, ds_encb, ds_w0,
                                      Ptop, Pbot, acc, Nn);

    // ---- timesteps ----
    for (int t = 1; t < NTS; t++) {
        const float* fprev_in = (t == 1) ? F_initial : (const float*)Fprev;
        edge_mlp_tc_kernel<<<nb_edge, 256, SM_TOTAL>>>(Ptop, Pbot, ds_b0,
                                                       wbhi_ds, wblo_ds, ds_bh,
                                                       srcp, dstp, acc, E);
        int has_enc = (t + 1 < NTS) ? 1 : 0;
        fused_ds_kernel<<<nb_fuse, 256>>>(acc, ds_dw1, ds_db1, ds_dw2, ds_db2,
                                          fprev_in, dtp, Fprev, outF, outFd,
                                          t - 1, nsteps,
                                          has_enc, meshh, F_boundary, t + 1,
                                          ds_encw, ds_encb, ds_w0,
                                          Ptop, Pbot, acc, Nn);
    }
}

// round 16
// speedup vs baseline: 1.1441x; 1.1441x over previous
#include <cuda_runtime.h>
#include <cuda_bf16.h>
#include <cstdint>

#define HID   64
#define NFLD  2
#define NHH   32
#define NMF   8
#define NTS   4
#define NLAY  9
#define MAXN  10016

// ---------------- scratch (device globals; no allocation allowed) -----------
__device__ float g_Ptop[MAXN * HID];
__device__ float g_Pbot[MAXN * HID];
__device__ float g_acc [MAXN * HID];
__device__ float g_meshh[MAXN * NHH];
__device__ float g_Fprev[MAXN * NFLD];
// pre-converted edge weights: [set][layer][n][k] bf16 hi/lo, chunk-swizzled
__device__ __align__(16) __nv_bfloat16 g_WBhi[2][NLAY * HID * HID];
__device__ __align__(16) __nv_bfloat16 g_WBlo[2][NLAY * HID * HID];

// ---------------- helpers -----------------------------------------------------
__device__ __forceinline__ uint32_t s2u(const void* p) {
    uint32_t a;
    asm("{ .reg .u64 t; cvta.to.shared.u64 t, %1; cvt.u32.u64 %0, t; }"
        : "=r"(a) : "l"(p));
    return a;
}
__device__ __forceinline__ void ldsm4(uint32_t* r, uint32_t addr) {
    asm volatile("ldmatrix.sync.aligned.m8n8.x4.shared.b16 {%0,%1,%2,%3}, [%4];"
                 : "=r"(r[0]), "=r"(r[1]), "=r"(r[2]), "=r"(r[3]) : "r"(addr));
}
__device__ __forceinline__ void stsm4(uint32_t addr, const uint32_t* r) {
    asm volatile("stmatrix.sync.aligned.m8n8.x4.shared.b16 [%0], {%1,%2,%3,%4};"
                 :: "r"(addr), "r"(r[0]), "r"(r[1]), "r"(r[2]), "r"(r[3]) : "memory");
}
__device__ __forceinline__ void mma16816(float* c, const uint32_t* a, const uint32_t* b) {
    asm volatile("mma.sync.aligned.m16n8k16.row.col.f32.bf16.bf16.f32 "
                 "{%0,%1,%2,%3}, {%4,%5,%6,%7}, {%8,%9}, {%0,%1,%2,%3};"
                 : "+f"(c[0]), "+f"(c[1]), "+f"(c[2]), "+f"(c[3])
                 : "r"(a[0]), "r"(a[1]), "r"(a[2]), "r"(a[3]), "r"(b[0]), "r"(b[1]));
}
// pack 2 floats -> bf16x2 (low half = first arg), round-nearest-even
__device__ __forceinline__ uint32_t cvt2bf(float lo, float hi_) {
    uint32_t r;
    asm("cvt.rn.bf16x2.f32 %0, %1, %2;" : "=r"(r) : "f"(hi_), "f"(lo));
    return r;
}
#define CP_ASYNC16(dst, src) \
    asm volatile("cp.async.ca.shared.global [%0], [%1], 16;" :: "r"(dst), "l"(src) : "memory")
#define CP_COMMIT() asm volatile("cp.async.commit_group;" ::: "memory")
#define CP_WAIT0()  asm volatile("cp.async.wait_group 0;" ::: "memory")

// ---------------- weight pre-conversion (both sets, one launch) --------------
__global__ void prep_wb_kernel(const float* __restrict__ W_md,
                               const float* __restrict__ W_ds,
                               __nv_bfloat16* __restrict__ hi,
                               __nv_bfloat16* __restrict__ lo)
{
    int idx = blockIdx.x * 256 + threadIdx.x;
    if (idx >= 2 * NLAY * HID * HID) return;
    int set = idx >= NLAY * HID * HID;
    int r0  = idx - set * NLAY * HID * HID;
    const float* Wh = set ? W_ds : W_md;
    int l = r0 >> 12, r = r0 & 4095;
    int j = r >> 6, k = r & 63;
    float w = Wh[l * 4096 + k * 64 + j];
    __nv_bfloat16 h = __float2bfloat16(w);
    __nv_bfloat16 lo_ = __float2bfloat16(w - __bfloat162float(h));
    int off = j * 128 + k * 2;
    int sw  = off ^ ((off >> 3) & 0x70);
    hi[set * NLAY * HID * HID + l * 4096 + (sw >> 1)] = h;
    lo[set * NLAY * HID * HID + l * 4096 + (sw >> 1)] = lo_;
}

// ---------------- per-node projection (mesh descriptor) ----------------------
__global__ void proj_md_kernel(const float* __restrict__ X,
                               const float* __restrict__ W0,
                               float* __restrict__ Ptop, float* __restrict__ Pbot,
                               float* __restrict__ acc, int Nn)
{
    int idx = blockIdx.x * blockDim.x + threadIdx.x;
    if (idx >= Nn * HID) return;
    int n = idx >> 6, j = idx & 63;
    float st0 = 0.f, st1 = 0.f, sb0 = 0.f, sb1 = 0.f;
#pragma unroll
    for (int k = 0; k < NMF; k += 2) {
        float x0 = X[n * NMF + k], x1 = X[n * NMF + k + 1];
        st0 = fmaf(x0, W0[k * HID + j], st0);
        st1 = fmaf(x1, W0[(k + 1) * HID + j], st1);
        sb0 = fmaf(x0, W0[(NMF + k) * HID + j], sb0);
        sb1 = fmaf(x1, W0[(NMF + k + 1) * HID + j], sb1);
    }
    Ptop[idx] = st0 + st1;
    Pbot[idx] = sb0 + sb1;
    acc[idx]  = 0.f;
}

// ---------------- fused node encoder + projection (ds) -----------------------
__global__ void encproj_ds_kernel(const float* __restrict__ meshh,
                                  const float* __restrict__ Fprev,
                                  const float* __restrict__ Fb, int t,
                                  const float* __restrict__ encW,
                                  const float* __restrict__ encb,
                                  const float* __restrict__ W0,
                                  float* __restrict__ Ptop, float* __restrict__ Pbot,
                                  float* __restrict__ acc, int Nn)
{
    __shared__ float sh[4][64];
    int tid = threadIdx.x;
    int q = tid >> 6, j = tid & 63;
    int n = blockIdx.x * 4 + q;
    float s0 = encb[j], s1 = 0.f;
    if (n < Nn) {
#pragma unroll
        for (int k = 0; k < NHH; k += 2) {
            s0 = fmaf(meshh[n * NHH + k],     encW[k * HID + j],       s0);
            s1 = fmaf(meshh[n * NHH + k + 1], encW[(k + 1) * HID + j], s1);
        }
        s0 = fmaf(Fprev[n * NFLD + 0], encW[(NHH + 0) * HID + j], s0);
        s1 = fmaf(Fprev[n * NFLD + 1], encW[(NHH + 1) * HID + j], s1);
        s0 = fmaf(Fb[n * NTS + t],     encW[(NHH + 2) * HID + j], s0);
    }
    sh[q][j] = fmaxf(s0 + s1, 0.f);
    __syncthreads();
    if (n < Nn) {
        float st0 = 0.f, st1 = 0.f, sb0 = 0.f, sb1 = 0.f;
#pragma unroll 8
        for (int k = 0; k < HID; k += 2) {
            float x0 = sh[q][k], x1 = sh[q][k + 1];
            st0 = fmaf(x0, W0[k * HID + j], st0);
            st1 = fmaf(x1, W0[(k + 1) * HID + j], st1);
            sb0 = fmaf(x0, W0[(HID + k) * HID + j], sb0);
            sb1 = fmaf(x1, W0[(HID + k + 1) * HID + j], sb1);
        }
        int idx = n * HID + j;
        Ptop[idx] = st0 + st1;
        Pbot[idx] = sb0 + sb1;
        acc[idx]  = 0.f;
    }
}

// ---------------- HMMA edge MLP, register-resident activations ----------------
// 128 threads (4 warps), 128e tile; warp = 32e x 64c (full width).
// A-hi fragments live in REGISTERS across all 9 layers (C-frag == A-frag
// layout, validated by R13's stsm->ldsm round trip). A-lo round-trips through
// warp-PRIVATE smem (stsm/ldsm, no barrier). W cp.async double-buffered;
// ONE __syncthreads per layer (W lifecycle only). bf16x3 split, bias in C.
#define SM_AH0   0          // 16KB: layer-0 A-hi staging (dead after preload)
#define SM_ALO   16384      // 16KB: A-lo (warp-private rows, in-place)
#define SM_W0    32768      // 16KB: W buffer 0 (hi 8K | lo 8K)
#define SM_W1    49152      // 16KB: W buffer 1
#define SM_BIAS  65536      // 2304B
#define SM_TOTAL 67840

__global__ void __launch_bounds__(128, 3)
edge_mlp_tc_kernel(const float* __restrict__ Ptop, const float* __restrict__ Pbot,
                   const float* __restrict__ b0,
                   const __nv_bfloat16* __restrict__ WBhi,
                   const __nv_bfloat16* __restrict__ WBlo,
                   const float* __restrict__ Bh,
                   const int* __restrict__ srcp, const int* __restrict__ dstp,
                   float* __restrict__ acc, int E)
{
    extern __shared__ __align__(1024) char sm[];
    const int tid = threadIdx.x, lane = tid & 31, w = tid >> 5;
    const int e0 = blockIdx.x * 128;

    // ---- stage layer-0 weights via cp.async (overlaps gather) ----
    {
        uint32_t wb = s2u(sm + SM_W0);
        const char* gh = (const char*)WBhi;
        const char* gl = (const char*)WBlo;
        for (int i = tid; i < 512; i += 128) {
            CP_ASYNC16(wb + i * 16,        gh + i * 16);
            CP_ASYNC16(wb + 8192 + i * 16, gl + i * 16);
        }
        CP_COMMIT();
        for (int i = tid; i < NLAY * HID; i += 128)
            ((float*)(sm + SM_BIAS))[i] = Bh[i];
    }

    // ---- gather h0 = relu(Ptop[dst]+Pbot[src]+b0) -> AH0 (hi) + ALO (lo) ----
    for (int u = tid; u < 128 * 8; u += 128) {
        int e = u & 127, oct = u >> 7;
        int ge = e0 + e;
        float v[8];
        if (ge < E) {
            int d = dstp[ge], s = srcp[ge];
            float4 t0 = *(const float4*)(Ptop + d * HID + oct * 8);
            float4 t1 = *(const float4*)(Ptop + d * HID + oct * 8 + 4);
            float4 p0 = *(const float4*)(Pbot + s * HID + oct * 8);
            float4 p1 = *(const float4*)(Pbot + s * HID + oct * 8 + 4);
            float4 c0 = *(const float4*)(b0 + oct * 8);
            float4 c1 = *(const float4*)(b0 + oct * 8 + 4);
            v[0] = fmaxf(t0.x + p0.x + c0.x, 0.f);
            v[1] = fmaxf(t0.y + p0.y + c0.y, 0.f);
            v[2] = fmaxf(t0.z + p0.z + c0.z, 0.f);
            v[3] = fmaxf(t0.w + p0.w + c0.w, 0.f);
            v[4] = fmaxf(t1.x + p1.x + c1.x, 0.f);
            v[5] = fmaxf(t1.y + p1.y + c1.y, 0.f);
            v[6] = fmaxf(t1.z + p1.z + c1.z, 0.f);
            v[7] = fmaxf(t1.w + p1.w + c1.w, 0.f);
        } else {
#pragma unroll
            for (int i = 0; i < 8; i++) v[i] = 0.f;
        }
        uint32_t hw[4], lw[4];
#pragma unroll
        for (int i = 0; i < 4; i++) {
            float a = v[2 * i], b = v[2 * i + 1];
            uint32_t h = cvt2bf(a, b);
            float haf = __uint_as_float(h << 16);
            float hbf = __uint_as_float(h & 0xFFFF0000u);
            hw[i] = h;
            lw[i] = cvt2bf(a - haf, b - hbf);
        }
        int sw = (oct ^ (e & 7)) * 16;
        *(uint4*)(sm + SM_AH0 + e * 128 + sw) = make_uint4(hw[0], hw[1], hw[2], hw[3]);
        *(uint4*)(sm + SM_ALO + e * 128 + sw) = make_uint4(lw[0], lw[1], lw[2], lw[3]);
    }
    CP_WAIT0();
    __syncthreads();   // AH0/ALO + W0 + bias ready

    // ---- per-lane fragment address components ----
    const int rA  = lane & 15, khA = lane >> 4;
    const int eloc = w * 32 + rA;                           // mt0 row
    const uint32_t a_base = (uint32_t)(eloc * 128);         // + mt*2048
    int axoff[4];
#pragma unroll
    for (int kt = 0; kt < 4; kt++)
        axoff[kt] = (((kt << 1) + khA) ^ (eloc & 7)) << 4;

    const int nB = (lane & 7) + ((lane >> 4) << 3);         // + np*16
    const int khB = (lane >> 3) & 1;
    int wxoff[4];
#pragma unroll
    for (int kt = 0; kt < 4; kt++)
        wxoff[kt] = (((kt << 1) + khB) ^ (lane & 7)) << 4;

    const uint32_t AH0B = s2u(sm + SM_AH0);
    const uint32_t ALOB = s2u(sm + SM_ALO);

    // ---- preload layer-0 A-hi fragments into registers ----
    uint32_t ah[4][2][4];
#pragma unroll
    for (int kt = 0; kt < 4; kt++)
#pragma unroll
        for (int mt = 0; mt < 2; mt++)
            ldsm4(ah[kt][mt], AH0B + a_base + mt * 2048 + axoff[kt]);

    for (int l = 0; l < NLAY; l++) {
        const uint32_t Wcur = s2u(sm + ((l & 1) ? SM_W1 : SM_W0));

        // prefetch next layer's weights into the other buffer
        if (l + 1 < NLAY) {
            uint32_t wb = s2u(sm + ((l & 1) ? SM_W0 : SM_W1));
            const char* gh = (const char*)(WBhi + (l + 1) * 4096);
            const char* gl = (const char*)(WBlo + (l + 1) * 4096);
            for (int i = tid; i < 512; i += 128) {
                CP_ASYNC16(wb + i * 16,        gh + i * 16);
                CP_ASYNC16(wb + 8192 + i * 16, gl + i * 16);
            }
            CP_COMMIT();
        }

        // ---- C init from bias ----
        const float* bsl = (const float*)(sm + SM_BIAS) + l * HID;
        float C[2][8][4];
#pragma unroll
        for (int nt = 0; nt < 8; nt++) {
            float2 bb = *(const float2*)(bsl + nt * 8 + (lane & 3) * 2);
#pragma unroll
            for (int mt = 0; mt < 2; mt++) {
                C[mt][nt][0] = bb.x; C[mt][nt][1] = bb.y;
                C[mt][nt][2] = bb.x; C[mt][nt][3] = bb.y;
            }
        }

        // ---- main loop: A-hi from regs, A-lo from warp-private smem ----
#pragma unroll
        for (int kt = 0; kt < 4; kt++) {
            uint32_t alr[2][4];
            ldsm4(alr[0], ALOB + a_base + axoff[kt]);
            ldsm4(alr[1], ALOB + a_base + 2048 + axoff[kt]);
#pragma unroll
            for (int np = 0; np < 4; np++) {
                uint32_t t4[4];
                uint32_t woff = (uint32_t)((np * 16 + nB) * 128);
                ldsm4(t4, Wcur + woff + wxoff[kt]);              // W hi
                mma16816(C[0][2 * np],     ah[kt][0], t4);
                mma16816(C[0][2 * np + 1], ah[kt][0], t4 + 2);
                mma16816(C[1][2 * np],     ah[kt][1], t4);
                mma16816(C[1][2 * np + 1], ah[kt][1], t4 + 2);
                mma16816(C[0][2 * np],     alr[0],    t4);
                mma16816(C[0][2 * np + 1], alr[0],    t4 + 2);
                mma16816(C[1][2 * np],     alr[1],    t4);
                mma16816(C[1][2 * np + 1], alr[1],    t4 + 2);
                ldsm4(t4, Wcur + 8192 + woff + wxoff[kt]);       // W lo
                mma16816(C[0][2 * np],     ah[kt][0], t4);
                mma16816(C[0][2 * np + 1], ah[kt][0], t4 + 2);
                mma16816(C[1][2 * np],     ah[kt][1], t4);
                mma16816(C[1][2 * np + 1], ah[kt][1], t4 + 2);
            }
        }

        if (l + 1 < NLAY) {
            // ---- convert C -> next-layer A: hi into regs, lo into smem ----
#pragma unroll
            for (int kt = 0; kt < 4; kt++) {
#pragma unroll
                for (int mt = 0; mt < 2; mt++) {
                    uint32_t alw[4];
#pragma unroll
                    for (int q = 0; q < 4; q++) {
                        // q: 0 -> C[2kt][0,1], 1 -> C[2kt][2,3],
                        //    2 -> C[2kt+1][0,1], 3 -> C[2kt+1][2,3]
                        const float* cp = C[mt][2 * kt + (q >> 1)];
                        float v0 = fmaxf(cp[(q & 1) * 2 + 0], 0.f);
                        float v1 = fmaxf(cp[(q & 1) * 2 + 1], 0.f);
                        uint32_t h = cvt2bf(v0, v1);
                        float h0f = __uint_as_float(h << 16);
                        float h1f = __uint_as_float(h & 0xFFFF0000u);
                        ah[kt][mt][q] = h;
                        alw[q] = cvt2bf(v0 - h0f, v1 - h1f);
                    }
                    stsm4(ALOB + a_base + mt * 2048 + axoff[kt], alw);
                }
            }
            CP_WAIT0();
            __syncthreads();   // W(l+1) ready; all warps done with Wcur
        } else {
            // ---- last layer: fp32 atomic scatter by src ----
#pragma unroll
            for (int mt = 0; mt < 2; mt++) {
#pragma unroll
                for (int half = 0; half < 2; half++) {
                    int e  = e0 + w * 32 + mt * 16 + (lane >> 2) + half * 8;
                    if (e < E) {
                        int node = srcp[e];
                        float* ap = acc + node * HID;
#pragma unroll
                        for (int nt = 0; nt < 8; nt++) {
                            int n = nt * 8 + (lane & 3) * 2;
                            atomicAdd(ap + n,     C[mt][nt][half * 2 + 0]);
                            atomicAdd(ap + n + 1, C[mt][nt][half * 2 + 1]);
                        }
                    }
                }
            }
        }
    }
}

// ---------------- node decoder (mesh descriptor) -----------------------------
__global__ void dec_md_kernel(const float* __restrict__ acc,
                              const float* __restrict__ dw1, const float* __restrict__ db1,
                              const float* __restrict__ dw2, const float* __restrict__ db2,
                              float* __restrict__ meshh, int Nn)
{
    __shared__ float t1[4][64];
    int tid = threadIdx.x;
    int q = tid >> 6, j = tid & 63;
    int n = blockIdx.x * 4 + q;
    float s0 = db1[j], s1 = 0.f;
    if (n < Nn) {
#pragma unroll 8
        for (int k = 0; k < HID; k += 2) {
            s0 = fmaf(acc[n * HID + k],     dw1[k * HID + j],       s0);
            s1 = fmaf(acc[n * HID + k + 1], dw1[(k + 1) * HID + j], s1);
        }
    }
    t1[q][j] = fmaxf(s0 + s1, 0.f);
    __syncthreads();
    if (tid < 128) {
        int q2 = tid >> 5, j2 = tid & 31;
        int n2 = blockIdx.x * 4 + q2;
        if (n2 < Nn) {
            float o0 = db2[j2], o1 = 0.f;
#pragma unroll 8
            for (int k = 0; k < HID; k += 2) {
                o0 = fmaf(t1[q2][k],     dw2[k * NHH + j2],       o0);
                o1 = fmaf(t1[q2][k + 1], dw2[(k + 1) * NHH + j2], o1);
            }
            meshh[n2 * NHH + j2] = o0 + o1;
        }
    }
}

// ---------------- node decoder (ds) + Euler step + output --------------------
__global__ void dec_ds_kernel(const float* __restrict__ acc,
                              const float* __restrict__ dw1, const float* __restrict__ db1,
                              const float* __restrict__ dw2, const float* __restrict__ db2,
                              const float* __restrict__ Fprev_in,
                              const float* __restrict__ dtp,
                              float* __restrict__ Fprev_out,
                              float* __restrict__ outF, float* __restrict__ outFd,
                              int step, int nsteps, int Nn)
{
    __shared__ float t1[4][64];
    int tid = threadIdx.x;
    int q = tid >> 6, j = tid & 63;
    int n = blockIdx.x * 4 + q;
    float s0 = db1[j], s1 = 0.f;
    if (n < Nn) {
#pragma unroll 8
        for (int k = 0; k < HID; k += 2) {
            s0 = fmaf(acc[n * HID + k],     dw1[k * HID + j],       s0);
            s1 = fmaf(acc[n * HID + k + 1], dw1[(k + 1) * HID + j], s1);
        }
    }
    t1[q][j] = fmaxf(s0 + s1, 0.f);
    __syncthreads();
    if (tid < 8) {
        int q2 = tid >> 1, f = tid & 1;
        int n2 = blockIdx.x * 4 + q2;
        if (n2 < Nn) {
            float o0 = db2[f], o1 = 0.f;
#pragma unroll 8
            for (int k = 0; k < HID; k += 2) {
                o0 = fmaf(t1[q2][k],     dw2[k * NFLD + f],       o0);
                o1 = fmaf(t1[q2][k + 1], dw2[(k + 1) * NFLD + f], o1);
            }
            float o  = o0 + o1;
            float fp = Fprev_in[n2 * NFLD + f];
            float fc = fmaf(dtp[0], o, fp);
            outF [(n2 * nsteps + step) * NFLD + f] = fc;
            outFd[(n2 * nsteps + step) * NFLD + f] = o;
            Fprev_out[n2 * NFLD + f] = fc;
        }
    }
}

// ---------------- launch ------------------------------------------------------
extern "C" void kernel_launch(void* const* d_in, const int* in_sizes, int n_in,
                              void* d_out, int out_size)
{
    const float* F_initial     = (const float*)d_in[0];
    const float* mesh_features = (const float*)d_in[1];
    const int*   edge_index    = (const int*)  d_in[2];
    const float* F_boundary    = (const float*)d_in[3];
    const float* dtp           = (const float*)d_in[4];
    const float* md_w0  = (const float*)d_in[5];
    const float* md_b0  = (const float*)d_in[6];
    const float* md_wh  = (const float*)d_in[7];
    const float* md_bh  = (const float*)d_in[8];
    const float* md_dw1 = (const float*)d_in[9];
    const float* md_db1 = (const float*)d_in[10];
    const float* md_dw2 = (const float*)d_in[11];
    const float* md_db2 = (const float*)d_in[12];
    const float* ds_encw = (const float*)d_in[13];
    const float* ds_encb = (const float*)d_in[14];
    const float* ds_w0  = (const float*)d_in[15];
    const float* ds_b0  = (const float*)d_in[16];
    const float* ds_wh  = (const float*)d_in[17];
    const float* ds_bh  = (const float*)d_in[18];
    const float* ds_dw1 = (const float*)d_in[19];
    const float* ds_db1 = (const float*)d_in[20];
    const float* ds_dw2 = (const float*)d_in[21];
    const float* ds_db2 = (const float*)d_in[22];

    int Nn = in_sizes[0] / NFLD;
    int E  = in_sizes[2] / 2;

    float *Ptop, *Pbot, *acc, *meshh, *Fprev;
    __nv_bfloat16 *wbhi, *wblo;
    cudaGetSymbolAddress((void**)&Ptop,  g_Ptop);
    cudaGetSymbolAddress((void**)&Pbot,  g_Pbot);
    cudaGetSymbolAddress((void**)&acc,   g_acc);
    cudaGetSymbolAddress((void**)&meshh, g_meshh);
    cudaGetSymbolAddress((void**)&Fprev, g_Fprev);
    cudaGetSymbolAddress((void**)&wbhi,  g_WBhi);
    cudaGetSymbolAddress((void**)&wblo,  g_WBlo);

    cudaFuncSetAttribute(edge_mlp_tc_kernel,
                         cudaFuncAttributeMaxDynamicSharedMemorySize, SM_TOTAL);

    const int* srcp = edge_index;
    const int* dstp = edge_index + E;

    int nb_node = (Nn * HID + 255) / 256;
    int nb_dec  = (Nn + 3) / 4;
    int nsteps  = NTS - 1;
    int nb_edge = (E + 127) / 128;
    int nb_prep = (2 * NLAY * HID * HID + 255) / 256;

    float* outF  = (float*)d_out;
    float* outFd = outF + (size_t)out_size / 2;

    __nv_bfloat16* wbhi_md = wbhi;
    __nv_bfloat16* wblo_md = wblo;
    __nv_bfloat16* wbhi_ds = wbhi + NLAY * HID * HID;
    __nv_bfloat16* wblo_ds = wblo + NLAY * HID * HID;

    // ---- weight pre-conversion ----
    prep_wb_kernel<<<nb_prep, 256>>>(md_wh, ds_wh, wbhi, wblo);

    // ---- mesh descriptor pass ----
    proj_md_kernel<<<nb_node, 256>>>(mesh_features, md_w0, Ptop, Pbot, acc, Nn);
    edge_mlp_tc_kernel<<<nb_edge, 128, SM_TOTAL>>>(Ptop, Pbot, md_b0,
                                                   wbhi_md, wblo_md, md_bh,
                                                   srcp, dstp, acc, E);
    dec_md_kernel<<<nb_dec, 256>>>(acc, md_dw1, md_db1, md_dw2, md_db2, meshh, Nn);

    // ---- timesteps ----
    for (int t = 1; t < NTS; t++) {
        const float* fprev_in = (t == 1) ? F_initial : (const float*)Fprev;
        encproj_ds_kernel<<<nb_dec, 256>>>(meshh, fprev_in, F_boundary, t,
                                           ds_encw, ds_encb, ds_w0,
                                           Ptop, Pbot, acc, Nn);
        edge_mlp_tc_kernel<<<nb_edge, 128, SM_TOTAL>>>(Ptop, Pbot, ds_b0,
                                                       wbhi_ds, wblo_ds, ds_bh,
                                                       srcp, dstp, acc, E);
        dec_ds_kernel<<<nb_dec, 256>>>(acc, ds_dw1, ds_db1, ds_dw2, ds_db2,
                                       fprev_in, dtp, Fprev, outF, outFd,
                                       t - 1, nsteps, Nn);
    }
}

// round 17
// speedup vs baseline: 1.1802x; 1.0316x over previous
#include <cuda_runtime.h>
#include <cuda_bf16.h>
#include <cstdint>

#define HID   64
#define NFLD  2
#define NHH   32
#define NMF   8
#define NTS   4
#define NLAY  9
#define MAXN  10016

// ---------------- scratch (device globals; no allocation allowed) -----------
__device__ float g_Ptop[MAXN * HID];
__device__ float g_Pbot[MAXN * HID];
__device__ float g_acc [MAXN * HID];
__device__ float g_meshh[MAXN * NHH];
__device__ float g_Fprev[MAXN * NFLD];
// pre-converted edge weights: [set][layer][n][k] bf16 hi/lo, chunk-swizzled
__device__ __align__(16) __nv_bfloat16 g_WBhi[2][NLAY * HID * HID];
__device__ __align__(16) __nv_bfloat16 g_WBlo[2][NLAY * HID * HID];

// ---------------- helpers -----------------------------------------------------
__device__ __forceinline__ uint32_t s2u(const void* p) {
    uint32_t a;
    asm("{ .reg .u64 t; cvta.to.shared.u64 t, %1; cvt.u32.u64 %0, t; }"
        : "=r"(a) : "l"(p));
    return a;
}
__device__ __forceinline__ void ldsm4(uint32_t* r, uint32_t addr) {
    asm volatile("ldmatrix.sync.aligned.m8n8.x4.shared.b16 {%0,%1,%2,%3}, [%4];"
                 : "=r"(r[0]), "=r"(r[1]), "=r"(r[2]), "=r"(r[3]) : "r"(addr));
}
__device__ __forceinline__ void stsm4(uint32_t addr, const uint32_t* r) {
    asm volatile("stmatrix.sync.aligned.m8n8.x4.shared.b16 [%0], {%1,%2,%3,%4};"
                 :: "r"(addr), "r"(r[0]), "r"(r[1]), "r"(r[2]), "r"(r[3]) : "memory");
}
__device__ __forceinline__ void mma16816(float* c, const uint32_t* a, const uint32_t* b) {
    asm volatile("mma.sync.aligned.m16n8k16.row.col.f32.bf16.bf16.f32 "
                 "{%0,%1,%2,%3}, {%4,%5,%6,%7}, {%8,%9}, {%0,%1,%2,%3};"
                 : "+f"(c[0]), "+f"(c[1]), "+f"(c[2]), "+f"(c[3])
                 : "r"(a[0]), "r"(a[1]), "r"(a[2]), "r"(a[3]), "r"(b[0]), "r"(b[1]));
}
// pack 2 floats -> bf16x2 (low half = first arg), round-nearest-even
__device__ __forceinline__ uint32_t cvt2bf(float lo, float hi_) {
    uint32_t r;
    asm("cvt.rn.bf16x2.f32 %0, %1, %2;" : "=r"(r) : "f"(hi_), "f"(lo));
    return r;
}
#define CP_ASYNC16(dst, src) \
    asm volatile("cp.async.ca.shared.global [%0], [%1], 16;" :: "r"(dst), "l"(src) : "memory")
#define CP_COMMIT() asm volatile("cp.async.commit_group;" ::: "memory")
#define CP_WAIT0()  asm volatile("cp.async.wait_group 0;" ::: "memory")

// ---------------- weight pre-conversion (both sets, one launch) --------------
__global__ void prep_wb_kernel(const float* __restrict__ W_md,
                               const float* __restrict__ W_ds,
                               __nv_bfloat16* __restrict__ hi,
                               __nv_bfloat16* __restrict__ lo)
{
    int idx = blockIdx.x * 256 + threadIdx.x;
    if (idx >= 2 * NLAY * HID * HID) return;
    int set = idx >= NLAY * HID * HID;
    int r0  = idx - set * NLAY * HID * HID;
    const float* Wh = set ? W_ds : W_md;
    int l = r0 >> 12, r = r0 & 4095;
    int j = r >> 6, k = r & 63;
    float w = Wh[l * 4096 + k * 64 + j];
    __nv_bfloat16 h = __float2bfloat16(w);
    __nv_bfloat16 lo_ = __float2bfloat16(w - __bfloat162float(h));
    int off = j * 128 + k * 2;
    int sw  = off ^ ((off >> 3) & 0x70);
    hi[set * NLAY * HID * HID + l * 4096 + (sw >> 1)] = h;
    lo[set * NLAY * HID * HID + l * 4096 + (sw >> 1)] = lo_;
}

// ---------------- per-node projection (mesh descriptor), 16 nodes/block ------
__global__ void proj_md_kernel(const float* __restrict__ X,
                               const float* __restrict__ W0,
                               float* __restrict__ Ptop, float* __restrict__ Pbot,
                               float* __restrict__ acc, int Nn)
{
    int tid = threadIdx.x;
    int c4 = tid & 15, ln = tid >> 4;
    int n = blockIdx.x * 16 + ln;
    if (n >= Nn) return;
    const float4* Wv = (const float4*)W0;
    float4 st = make_float4(0.f, 0.f, 0.f, 0.f);
    float4 sb = make_float4(0.f, 0.f, 0.f, 0.f);
#pragma unroll
    for (int k = 0; k < NMF; k++) {
        float a = X[n * NMF + k];
        float4 wt = Wv[k * 16 + c4];
        float4 wb = Wv[(NMF + k) * 16 + c4];
        st.x = fmaf(a, wt.x, st.x); st.y = fmaf(a, wt.y, st.y);
        st.z = fmaf(a, wt.z, st.z); st.w = fmaf(a, wt.w, st.w);
        sb.x = fmaf(a, wb.x, sb.x); sb.y = fmaf(a, wb.y, sb.y);
        sb.z = fmaf(a, wb.z, sb.z); sb.w = fmaf(a, wb.w, sb.w);
    }
    ((float4*)Ptop)[n * 16 + c4] = st;
    ((float4*)Pbot)[n * 16 + c4] = sb;
    ((float4*)acc )[n * 16 + c4] = make_float4(0.f, 0.f, 0.f, 0.f);
}

// ---------------- fused node encoder + projection (ds), 16 nodes/block -------
__global__ void encproj_ds_kernel(const float* __restrict__ meshh,
                                  const float* __restrict__ Fprev,
                                  const float* __restrict__ Fb, int t,
                                  const float* __restrict__ encW,
                                  const float* __restrict__ encb,
                                  const float* __restrict__ W0,
                                  float* __restrict__ Ptop, float* __restrict__ Pbot,
                                  float* __restrict__ acc, int Nn)
{
    __shared__ float he[16][64];
    int tid = threadIdx.x;
    int c4 = tid & 15, ln = tid >> 4;
    int n = blockIdx.x * 16 + ln;
    const float4* Ev = (const float4*)encW;
    float4 s = ((const float4*)encb)[c4];
    if (n < Nn) {
#pragma unroll 8
        for (int k = 0; k < NHH; k++) {
            float a = meshh[n * NHH + k];
            float4 w = Ev[k * 16 + c4];
            s.x = fmaf(a, w.x, s.x); s.y = fmaf(a, w.y, s.y);
            s.z = fmaf(a, w.z, s.z); s.w = fmaf(a, w.w, s.w);
        }
        float a0 = Fprev[n * NFLD + 0], a1 = Fprev[n * NFLD + 1];
        float a2 = Fb[n * NTS + t];
        float4 w0 = Ev[(NHH + 0) * 16 + c4];
        float4 w1 = Ev[(NHH + 1) * 16 + c4];
        float4 w2 = Ev[(NHH + 2) * 16 + c4];
        s.x = fmaf(a0, w0.x, fmaf(a1, w1.x, fmaf(a2, w2.x, s.x)));
        s.y = fmaf(a0, w0.y, fmaf(a1, w1.y, fmaf(a2, w2.y, s.y)));
        s.z = fmaf(a0, w0.z, fmaf(a1, w1.z, fmaf(a2, w2.z, s.z)));
        s.w = fmaf(a0, w0.w, fmaf(a1, w1.w, fmaf(a2, w2.w, s.w)));
    }
    he[ln][c4 * 4 + 0] = fmaxf(s.x, 0.f);
    he[ln][c4 * 4 + 1] = fmaxf(s.y, 0.f);
    he[ln][c4 * 4 + 2] = fmaxf(s.z, 0.f);
    he[ln][c4 * 4 + 3] = fmaxf(s.w, 0.f);
    __syncthreads();
    if (n < Nn) {
        const float4* Wv = (const float4*)W0;
        float4 st = make_float4(0.f, 0.f, 0.f, 0.f);
        float4 sb = make_float4(0.f, 0.f, 0.f, 0.f);
#pragma unroll 8
        for (int k = 0; k < HID; k++) {
            float a = he[ln][k];
            float4 wt = Wv[k * 16 + c4];
            float4 wb = Wv[(HID + k) * 16 + c4];
            st.x = fmaf(a, wt.x, st.x); st.y = fmaf(a, wt.y, st.y);
            st.z = fmaf(a, wt.z, st.z); st.w = fmaf(a, wt.w, st.w);
            sb.x = fmaf(a, wb.x, sb.x); sb.y = fmaf(a, wb.y, sb.y);
            sb.z = fmaf(a, wb.z, sb.z); sb.w = fmaf(a, wb.w, sb.w);
        }
        ((float4*)Ptop)[n * 16 + c4] = st;
        ((float4*)Pbot)[n * 16 + c4] = sb;
        ((float4*)acc )[n * 16 + c4] = make_float4(0.f, 0.f, 0.f, 0.f);
    }
}

// ---------------- node decoder (mesh descriptor), 16 nodes/block -------------
__global__ void dec_md_kernel(const float* __restrict__ acc,
                              const float* __restrict__ dw1, const float* __restrict__ db1,
                              const float* __restrict__ dw2, const float* __restrict__ db2,
                              float* __restrict__ meshh, int Nn)
{
    __shared__ float t1[16][64];
    int tid = threadIdx.x;
    int c4 = tid & 15, ln = tid >> 4;
    int n = blockIdx.x * 16 + ln;
    const float4* W1v = (const float4*)dw1;
    float4 s = ((const float4*)db1)[c4];
    if (n < Nn) {
#pragma unroll 8
        for (int k = 0; k < HID; k++) {
            float a = acc[n * HID + k];
            float4 w = W1v[k * 16 + c4];
            s.x = fmaf(a, w.x, s.x); s.y = fmaf(a, w.y, s.y);
            s.z = fmaf(a, w.z, s.z); s.w = fmaf(a, w.w, s.w);
        }
    }
    t1[ln][c4 * 4 + 0] = fmaxf(s.x, 0.f);
    t1[ln][c4 * 4 + 1] = fmaxf(s.y, 0.f);
    t1[ln][c4 * 4 + 2] = fmaxf(s.z, 0.f);
    t1[ln][c4 * 4 + 3] = fmaxf(s.w, 0.f);
    __syncthreads();
    if (tid < 128) {
        int c2 = tid & 7, ln2 = tid >> 3;
        int n2 = blockIdx.x * 16 + ln2;
        if (n2 < Nn) {
            const float4* W2v = (const float4*)dw2;
            float4 o = ((const float4*)db2)[c2];
#pragma unroll 8
            for (int k = 0; k < HID; k++) {
                float a = t1[ln2][k];
                float4 w = W2v[k * 8 + c2];
                o.x = fmaf(a, w.x, o.x); o.y = fmaf(a, w.y, o.y);
                o.z = fmaf(a, w.z, o.z); o.w = fmaf(a, w.w, o.w);
            }
            ((float4*)meshh)[n2 * 8 + c2] = o;
        }
    }
}

// ---------------- node decoder (ds) + Euler step + output, 16 nodes/block ----
__global__ void dec_ds_kernel(const float* __restrict__ acc,
                              const float* __restrict__ dw1, const float* __restrict__ db1,
                              const float* __restrict__ dw2, const float* __restrict__ db2,
                              const float* __restrict__ Fprev_in,
                              const float* __restrict__ dtp,
                              float* __restrict__ Fprev_out,
                              float* __restrict__ outF, float* __restrict__ outFd,
                              int step, int nsteps, int Nn)
{
    __shared__ float t1[16][64];
    int tid = threadIdx.x;
    int c4 = tid & 15, ln = tid >> 4;
    int n = blockIdx.x * 16 + ln;
    const float4* W1v = (const float4*)dw1;
    float4 s = ((const float4*)db1)[c4];
    if (n < Nn) {
#pragma unroll 8
        for (int k = 0; k < HID; k++) {
            float a = acc[n * HID + k];
            float4 w = W1v[k * 16 + c4];
            s.x = fmaf(a, w.x, s.x); s.y = fmaf(a, w.y, s.y);
            s.z = fmaf(a, w.z, s.z); s.w = fmaf(a, w.w, s.w);
        }
    }
    t1[ln][c4 * 4 + 0] = fmaxf(s.x, 0.f);
    t1[ln][c4 * 4 + 1] = fmaxf(s.y, 0.f);
    t1[ln][c4 * 4 + 2] = fmaxf(s.z, 0.f);
    t1[ln][c4 * 4 + 3] = fmaxf(s.w, 0.f);
    __syncthreads();
    if (tid < 32) {
        int ln2 = tid >> 1, f = tid & 1;
        int n2 = blockIdx.x * 16 + ln2;
        if (n2 < Nn) {
            float o0 = db2[f], o1 = 0.f;
#pragma unroll 8
            for (int k = 0; k < HID; k += 2) {
                o0 = fmaf(t1[ln2][k],     dw2[k * NFLD + f],       o0);
                o1 = fmaf(t1[ln2][k + 1], dw2[(k + 1) * NFLD + f], o1);
            }
            float o  = o0 + o1;
            float fp = Fprev_in[n2 * NFLD + f];
            float fc = fmaf(dtp[0], o, fp);
            outF [(n2 * nsteps + step) * NFLD + f] = fc;
            outFd[(n2 * nsteps + step) * NFLD + f] = o;
            Fprev_out[n2 * NFLD + f] = fc;
        }
    }
}

// ---------------- HMMA edge MLP, register-resident activations ----------------
// (byte-identical to R16 — committed win; do not touch)
#define SM_AH0   0
#define SM_ALO   16384
#define SM_W0    32768
#define SM_W1    49152
#define SM_BIAS  65536
#define SM_TOTAL 67840

__global__ void __launch_bounds__(128, 3)
edge_mlp_tc_kernel(const float* __restrict__ Ptop, const float* __restrict__ Pbot,
                   const float* __restrict__ b0,
                   const __nv_bfloat16* __restrict__ WBhi,
                   const __nv_bfloat16* __restrict__ WBlo,
                   const float* __restrict__ Bh,
                   const int* __restrict__ srcp, const int* __restrict__ dstp,
                   float* __restrict__ acc, int E)
{
    extern __shared__ __align__(1024) char sm[];
    const int tid = threadIdx.x, lane = tid & 31, w = tid >> 5;
    const int e0 = blockIdx.x * 128;

    // ---- stage layer-0 weights via cp.async (overlaps gather) ----
    {
        uint32_t wb = s2u(sm + SM_W0);
        const char* gh = (const char*)WBhi;
        const char* gl = (const char*)WBlo;
        for (int i = tid; i < 512; i += 128) {
            CP_ASYNC16(wb + i * 16,        gh + i * 16);
            CP_ASYNC16(wb + 8192 + i * 16, gl + i * 16);
        }
        CP_COMMIT();
        for (int i = tid; i < NLAY * HID; i += 128)
            ((float*)(sm + SM_BIAS))[i] = Bh[i];
    }

    // ---- gather h0 = relu(Ptop[dst]+Pbot[src]+b0) -> AH0 (hi) + ALO (lo) ----
    for (int u = tid; u < 128 * 8; u += 128) {
        int e = u & 127, oct = u >> 7;
        int ge = e0 + e;
        float v[8];
        if (ge < E) {
            int d = dstp[ge], s = srcp[ge];
            float4 t0 = *(const float4*)(Ptop + d * HID + oct * 8);
            float4 t1 = *(const float4*)(Ptop + d * HID + oct * 8 + 4);
            float4 p0 = *(const float4*)(Pbot + s * HID + oct * 8);
            float4 p1 = *(const float4*)(Pbot + s * HID + oct * 8 + 4);
            float4 c0 = *(const float4*)(b0 + oct * 8);
            float4 c1 = *(const float4*)(b0 + oct * 8 + 4);
            v[0] = fmaxf(t0.x + p0.x + c0.x, 0.f);
            v[1] = fmaxf(t0.y + p0.y + c0.y, 0.f);
            v[2] = fmaxf(t0.z + p0.z + c0.z, 0.f);
            v[3] = fmaxf(t0.w + p0.w + c0.w, 0.f);
            v[4] = fmaxf(t1.x + p1.x + c1.x, 0.f);
            v[5] = fmaxf(t1.y + p1.y + c1.y, 0.f);
            v[6] = fmaxf(t1.z + p1.z + c1.z, 0.f);
            v[7] = fmaxf(t1.w + p1.w + c1.w, 0.f);
        } else {
#pragma unroll
            for (int i = 0; i < 8; i++) v[i] = 0.f;
        }
        uint32_t hw[4], lw[4];
#pragma unroll
        for (int i = 0; i < 4; i++) {
            float a = v[2 * i], b = v[2 * i + 1];
            uint32_t h = cvt2bf(a, b);
            float haf = __uint_as_float(h << 16);
            float hbf = __uint_as_float(h & 0xFFFF0000u);
            hw[i] = h;
            lw[i] = cvt2bf(a - haf, b - hbf);
        }
        int sw = (oct ^ (e & 7)) * 16;
        *(uint4*)(sm + SM_AH0 + e * 128 + sw) = make_uint4(hw[0], hw[1], hw[2], hw[3]);
        *(uint4*)(sm + SM_ALO + e * 128 + sw) = make_uint4(lw[0], lw[1], lw[2], lw[3]);
    }
    CP_WAIT0();
    __syncthreads();

    const int rA  = lane & 15, khA = lane >> 4;
    const int eloc = w * 32 + rA;
    const uint32_t a_base = (uint32_t)(eloc * 128);
    int axoff[4];
#pragma unroll
    for (int kt = 0; kt < 4; kt++)
        axoff[kt] = (((kt << 1) + khA) ^ (eloc & 7)) << 4;

    const int nB = (lane & 7) + ((lane >> 4) << 3);
    const int khB = (lane >> 3) & 1;
    int wxoff[4];
#pragma unroll
    for (int kt = 0; kt < 4; kt++)
        wxoff[kt] = (((kt << 1) + khB) ^ (lane & 7)) << 4;

    const uint32_t AH0B = s2u(sm + SM_AH0);
    const uint32_t ALOB = s2u(sm + SM_ALO);

    uint32_t ah[4][2][4];
#pragma unroll
    for (int kt = 0; kt < 4; kt++)
#pragma unroll
        for (int mt = 0; mt < 2; mt++)
            ldsm4(ah[kt][mt], AH0B + a_base + mt * 2048 + axoff[kt]);

    for (int l = 0; l < NLAY; l++) {
        const uint32_t Wcur = s2u(sm + ((l & 1) ? SM_W1 : SM_W0));

        if (l + 1 < NLAY) {
            uint32_t wb = s2u(sm + ((l & 1) ? SM_W0 : SM_W1));
            const char* gh = (const char*)(WBhi + (l + 1) * 4096);
            const char* gl = (const char*)(WBlo + (l + 1) * 4096);
            for (int i = tid; i < 512; i += 128) {
                CP_ASYNC16(wb + i * 16,        gh + i * 16);
                CP_ASYNC16(wb + 8192 + i * 16, gl + i * 16);
            }
            CP_COMMIT();
        }

        const float* bsl = (const float*)(sm + SM_BIAS) + l * HID;
        float C[2][8][4];
#pragma unroll
        for (int nt = 0; nt < 8; nt++) {
            float2 bb = *(const float2*)(bsl + nt * 8 + (lane & 3) * 2);
#pragma unroll
            for (int mt = 0; mt < 2; mt++) {
                C[mt][nt][0] = bb.x; C[mt][nt][1] = bb.y;
                C[mt][nt][2] = bb.x; C[mt][nt][3] = bb.y;
            }
        }

#pragma unroll
        for (int kt = 0; kt < 4; kt++) {
            uint32_t alr[2][4];
            ldsm4(alr[0], ALOB + a_base + axoff[kt]);
            ldsm4(alr[1], ALOB + a_base + 2048 + axoff[kt]);
#pragma unroll
            for (int np = 0; np < 4; np++) {
                uint32_t t4[4];
                uint32_t woff = (uint32_t)((np * 16 + nB) * 128);
                ldsm4(t4, Wcur + woff + wxoff[kt]);
                mma16816(C[0][2 * np],     ah[kt][0], t4);
                mma16816(C[0][2 * np + 1], ah[kt][0], t4 + 2);
                mma16816(C[1][2 * np],     ah[kt][1], t4);
                mma16816(C[1][2 * np + 1], ah[kt][1], t4 + 2);
                mma16816(C[0][2 * np],     alr[0],    t4);
                mma16816(C[0][2 * np + 1], alr[0],    t4 + 2);
                mma16816(C[1][2 * np],     alr[1],    t4);
                mma16816(C[1][2 * np + 1], alr[1],    t4 + 2);
                ldsm4(t4, Wcur + 8192 + woff + wxoff[kt]);
                mma16816(C[0][2 * np],     ah[kt][0], t4);
                mma16816(C[0][2 * np + 1], ah[kt][0], t4 + 2);
                mma16816(C[1][2 * np],     ah[kt][1], t4);
                mma16816(C[1][2 * np + 1], ah[kt][1], t4 + 2);
            }
        }

        if (l + 1 < NLAY) {
#pragma unroll
            for (int kt = 0; kt < 4; kt++) {
#pragma unroll
                for (int mt = 0; mt < 2; mt++) {
                    uint32_t alw[4];
#pragma unroll
                    for (int q = 0; q < 4; q++) {
                        const float* cp = C[mt][2 * kt + (q >> 1)];
                        float v0 = fmaxf(cp[(q & 1) * 2 + 0], 0.f);
                        float v1 = fmaxf(cp[(q & 1) * 2 + 1], 0.f);
                        uint32_t h = cvt2bf(v0, v1);
                        float h0f = __uint_as_float(h << 16);
                        float h1f = __uint_as_float(h & 0xFFFF0000u);
                        ah[kt][mt][q] = h;
                        alw[q] = cvt2bf(v0 - h0f, v1 - h1f);
                    }
                    stsm4(ALOB + a_base + mt * 2048 + axoff[kt], alw);
                }
            }
            CP_WAIT0();
            __syncthreads();
        } else {
#pragma unroll
            for (int mt = 0; mt < 2; mt++) {
#pragma unroll
                for (int half = 0; half < 2; half++) {
                    int e  = e0 + w * 32 + mt * 16 + (lane >> 2) + half * 8;
                    if (e < E) {
                        int node = srcp[e];
                        float* ap = acc + node * HID;
#pragma unroll
                        for (int nt = 0; nt < 8; nt++) {
                            int n = nt * 8 + (lane & 3) * 2;
                            atomicAdd(ap + n,     C[mt][nt][half * 2 + 0]);
                            atomicAdd(ap + n + 1, C[mt][nt][half * 2 + 1]);
                        }
                    }
                }
            }
        }
    }
}

// ---------------- launch ------------------------------------------------------
extern "C" void kernel_launch(void* const* d_in, const int* in_sizes, int n_in,
                              void* d_out, int out_size)
{
    const float* F_initial     = (const float*)d_in[0];
    const float* mesh_features = (const float*)d_in[1];
    const int*   edge_index    = (const int*)  d_in[2];
    const float* F_boundary    = (const float*)d_in[3];
    const float* dtp           = (const float*)d_in[4];
    const float* md_w0  = (const float*)d_in[5];
    const float* md_b0  = (const float*)d_in[6];
    const float* md_wh  = (const float*)d_in[7];
    const float* md_bh  = (const float*)d_in[8];
    const float* md_dw1 = (const float*)d_in[9];
    const float* md_db1 = (const float*)d_in[10];
    const float* md_dw2 = (const float*)d_in[11];
    const float* md_db2 = (const float*)d_in[12];
    const float* ds_encw = (const float*)d_in[13];
    const float* ds_encb = (const float*)d_in[14];
    const float* ds_w0  = (const float*)d_in[15];
    const float* ds_b0  = (const float*)d_in[16];
    const float* ds_wh  = (const float*)d_in[17];
    const float* ds_bh  = (const float*)d_in[18];
    const float* ds_dw1 = (const float*)d_in[19];
    const float* ds_db1 = (const float*)d_in[20];
    const float* ds_dw2 = (const float*)d_in[21];
    const float* ds_db2 = (const float*)d_in[22];

    int Nn = in_sizes[0] / NFLD;
    int E  = in_sizes[2] / 2;

    float *Ptop, *Pbot, *acc, *meshh, *Fprev;
    __nv_bfloat16 *wbhi, *wblo;
    cudaGetSymbolAddress((void**)&Ptop,  g_Ptop);
    cudaGetSymbolAddress((void**)&Pbot,  g_Pbot);
    cudaGetSymbolAddress((void**)&acc,   g_acc);
    cudaGetSymbolAddress((void**)&meshh, g_meshh);
    cudaGetSymbolAddress((void**)&Fprev, g_Fprev);
    cudaGetSymbolAddress((void**)&wbhi,  g_WBhi);
    cudaGetSymbolAddress((void**)&wblo,  g_WBlo);

    cudaFuncSetAttribute(edge_mlp_tc_kernel,
                         cudaFuncAttributeMaxDynamicSharedMemorySize, SM_TOTAL);

    const int* srcp = edge_index;
    const int* dstp = edge_index + E;

    int nb_n16  = (Nn + 15) / 16;
    int nsteps  = NTS - 1;
    int nb_edge = (E + 127) / 128;
    int nb_prep = (2 * NLAY * HID * HID + 255) / 256;

    float* outF  = (float*)d_out;
    float* outFd = outF + (size_t)out_size / 2;

    __nv_bfloat16* wbhi_md = wbhi;
    __nv_bfloat16* wblo_md = wblo;
    __nv_bfloat16* wbhi_ds = wbhi + NLAY * HID * HID;
    __nv_bfloat16* wblo_ds = wblo + NLAY * HID * HID;

    // ---- weight pre-conversion ----
    prep_wb_kernel<<<nb_prep, 256>>>(md_wh, ds_wh, wbhi, wblo);

    // ---- mesh descriptor pass ----
    proj_md_kernel<<<nb_n16, 256>>>(mesh_features, md_w0, Ptop, Pbot, acc, Nn);
    edge_mlp_tc_kernel<<<nb_edge, 128, SM_TOTAL>>>(Ptop, Pbot, md_b0,
                                                   wbhi_md, wblo_md, md_bh,
                                                   srcp, dstp, acc, E);
    dec_md_kernel<<<nb_n16, 256>>>(acc, md_dw1, md_db1, md_dw2, md_db2, meshh, Nn);

    // ---- timesteps ----
    for (int t = 1; t < NTS; t++) {
        const float* fprev_in = (t == 1) ? F_initial : (const float*)Fprev;
        encproj_ds_kernel<<<nb_n16, 256>>>(meshh, fprev_in, F_boundary, t,
                                           ds_encw, ds_encb, ds_w0,
                                           Ptop, Pbot, acc, Nn);
        edge_mlp_tc_kernel<<<nb_edge, 128, SM_TOTAL>>>(Ptop, Pbot, ds_b0,
                                                       wbhi_ds, wblo_ds, ds_bh,
                                                       srcp, dstp, acc, E);
        dec_ds_kernel<<<nb_n16, 256>>>(acc, ds_dw1, ds_db1, ds_dw2, ds_db2,
                                       fprev_in, dtp, Fprev, outF, outFd,
                                       t - 1, nsteps, Nn);
    }
}